// round 13
// baseline (speedup 1.0000x reference)
#include <cuda_runtime.h>
#include <cuda_fp16.h>
#include <cstdint>

#define N_IMG 16
#define C_IN  256
#define HW    128
#define C_OUT 128
#define HALO  130

// Scratch (module-load allocated; zero-initialized => halo stays zero forever)
__device__ __align__(1024) __half g_xb[(size_t)N_IMG * HALO * HALO * C_IN];
// Winograd-transformed weights, B-fragment order: [coord4][chunk12][kt4][nt16][lane32]
__device__ __align__(16) uint2 g_wfrag[4 * 12 * 4 * 16 * 32];
__device__ float g_alpha[C_OUT];

__device__ __forceinline__ float sgnf(float v) {
    return (v > 0.f) ? 1.f : ((v < 0.f) ? -1.f : 0.f);
}

// ---------------------------------------------------------------------------
// Kernel 1: sign(x) NCHW f32 -> NHWC f16 with +1 halo offset (zero padding)
// ---------------------------------------------------------------------------
__global__ void pack_x_kernel(const float* __restrict__ x) {
    __shared__ float tile[64][33];
    int nh = blockIdx.z;              // n*128 + h
    int n = nh >> 7, h = nh & 127;
    int wt = blockIdx.y;              // 0..3  (w tile of 32)
    int ct = blockIdx.x;              // 0..3  (c tile of 64)
    int tx = threadIdx.x, ty = threadIdx.y;

#pragma unroll
    for (int j = 0; j < 8; j++) {
        int cl = ty + j * 8;          // 0..63
        float v = x[(((size_t)(n * C_IN + ct * 64 + cl)) * HW + h) * HW + wt * 32 + tx];
        tile[cl][tx] = sgnf(v);
    }
    __syncthreads();
#pragma unroll
    for (int j = 0; j < 4; j++) {
        int wl = ty + j * 8;          // 0..31
        __half2 hv = __floats2half2_rn(tile[tx * 2][wl], tile[tx * 2 + 1][wl]);
        size_t dsth2 = ((((size_t)n * HALO + (h + 1)) * HALO + (wt * 32 + wl + 1)) * C_IN
                        + ct * 64) >> 1;
        reinterpret_cast<__half2*>(g_xb)[dsth2 + tx] = hv;
    }
}

// ---------------------------------------------------------------------------
// Kernel 2: sign(W) OIHW -> Winograd F(2,3) weight transform along kx,
//   packed in mma.m16n8k16 B-fragment order.
//   U0 = g0, U1 = (g0+g1+g2)/2, U2 = (g0-g1+g2)/2, U3 = g2  (g = sign(w))
// ---------------------------------------------------------------------------
__global__ void pack_w_kernel(const float* __restrict__ w) {
    int g = blockIdx.x * 256 + threadIdx.x;    // 98304 total
    int lane = g & 31;
    int nt   = (g >> 5) & 15;
    int kt   = (g >> 9) & 3;
    int idx  = g >> 11;                        // 0..47 = c*12 + chunk
    int c = idx / 12, chunk = idx % 12;
    int ky = chunk >> 2, cc = chunk & 3;

    int ci0 = cc * 64 + kt * 16 + (lane & 3) * 2;
    int co  = nt * 8 + (lane >> 2);

    uint32_t bits[4];
    int cis[4] = {ci0, ci0 + 1, ci0 + 8, ci0 + 9};
#pragma unroll
    for (int j = 0; j < 4; j++) {
        const float* wp = w + ((size_t)(co * C_IN + cis[j]) * 3 + ky) * 3;
        float g0 = sgnf(wp[0]), g1 = sgnf(wp[1]), g2 = sgnf(wp[2]);
        float u = (c == 0) ? g0
                : (c == 1) ? 0.5f * (g0 + g1 + g2)
                : (c == 2) ? 0.5f * (g0 - g1 + g2)
                :            g2;
        __half hu = __float2half(u);
        bits[j] = (uint32_t)*reinterpret_cast<uint16_t*>(&hu);
    }
    g_wfrag[g] = make_uint2(bits[0] | (bits[1] << 16), bits[2] | (bits[3] << 16));
}

// ---------------------------------------------------------------------------
// Kernel 3: alpha[co] = mean |W[co,:,:,:]|
// ---------------------------------------------------------------------------
__global__ void alpha_kernel(const float* __restrict__ w) {
    __shared__ float red[256];
    int co = blockIdx.x;
    float s = 0.f;
    for (int i = threadIdx.x; i < 2304; i += 256)
        s += fabsf(w[(size_t)co * 2304 + i]);
    red[threadIdx.x] = s;
    __syncthreads();
    for (int o = 128; o > 0; o >>= 1) {
        if (threadIdx.x < o) red[threadIdx.x] += red[threadIdx.x + o];
        __syncthreads();
    }
    if (threadIdx.x == 0) g_alpha[co] = red[0] / 2304.f;
}

// ---------------------------------------------------------------------------
// Kernel 4: Winograd-F(2,3)-along-w conv, 8 warps, 64x64 warp tiles, 2 CTA/SM.
//   Transform for chunk s+1 finely interleaved into chunk s's MMA stream:
//   LDS early (latency under MMAs), HADD2+STS emitted between mt groups, so
//   LSU work drains inside tensor windows instead of serializing after them.
// ---------------------------------------------------------------------------
#define A_PAD 72                          // halves; 144B row stride
#define A_ROWS 130
#define RAWSZ (A_ROWS * A_PAD * 2)        // 18720
#define VCOORD_SZ (64 * A_PAD * 2)        // 9216 bytes
#define VBUF_SZ (4 * VCOORD_SZ)           // 36864
#define V_OFF (2 * RAWSZ)                 // 37440
#define SMEM_DYN (V_OFF + 2 * VBUF_SZ)    // 111168 (x2 CTAs = 222336 <= 228KB)

__device__ __forceinline__ void issue_raw(char* smem, int tid, int n, int h, int s) {
    int ky = s >> 2, cc = s & 3;
    char* sR = smem + (s & 1) * RAWSZ;
    const __half* gx = &g_xb[(((size_t)n * HALO + h + ky) * HALO) * C_IN + cc * 64];
#pragma unroll
    for (int v = 0; v < 5; v++) {
        int u = tid + v * 256;            // 1040 units of 16B (130 rows x 8)
        if (u < A_ROWS * 8) {
            int row = u >> 3, seg = u & 7;
            uint32_t sa = (uint32_t)__cvta_generic_to_shared(sR + row * 144 + seg * 16);
            const void* ga = gx + (size_t)row * C_IN + seg * 8;
            asm volatile("cp.async.cg.shared.global [%0], [%1], 16;\n" :: "r"(sa), "l"(ga));
        }
    }
    asm volatile("cp.async.commit_group;\n");
}

// Transform split into register-load and compute+store halves (interleavable).
// Item idx in [0,2048): t = idx>>5 (tile), l = idx&31 (ci-h2 lane).
__device__ __forceinline__ void tr_load(char* smem, int s, int idx, __half2* d) {
    const __half2* sR = (const __half2*)(smem + (s & 1) * RAWSZ);  // 36 h2/row
    int t = idx >> 5, l = idx & 31;
    d[0] = sR[(2 * t + 0) * 36 + l];
    d[1] = sR[(2 * t + 1) * 36 + l];
    d[2] = sR[(2 * t + 2) * 36 + l];
    d[3] = sR[(2 * t + 3) * 36 + l];
}
__device__ __forceinline__ void tr_store(char* smem, int s, int idx, const __half2* d) {
    __half2* pv = (__half2*)(smem + V_OFF + (s & 1) * VBUF_SZ);    // 36 h2/tile-row
    int t = idx >> 5, l = idx & 31;
    pv[0 * 2304 + t * 36 + l] = __hsub2(d[0], d[2]);
    pv[1 * 2304 + t * 36 + l] = __hadd2(d[1], d[2]);
    pv[2 * 2304 + t * 36 + l] = __hsub2(d[2], d[1]);
    pv[3 * 2304 + t * 36 + l] = __hsub2(d[1], d[3]);
}

__global__ void __launch_bounds__(256, 2) conv_kernel(float* __restrict__ out) {
    extern __shared__ char smem[];
    int tid = threadIdx.x;
    int lane = tid & 31, wid = tid >> 5;
    int c  = wid >> 1;        // coord 0..3
    int n2 = wid & 1;         // N-half 0..1 (64 couts)
    int h = blockIdx.x, n = blockIdx.y;

    uint32_t acc[4][8][2];    // f16x2 accumulators [mtile][ntile]
#pragma unroll
    for (int a = 0; a < 4; a++)
#pragma unroll
        for (int b = 0; b < 8; b++) { acc[a][b][0] = 0u; acc[a][b][1] = 0u; }

    // Double-buffered B fragments (per kt). Preload chunk 0, kt 0.
    uint2 bfr[2][8];
#pragma unroll
    for (int nt = 0; nt < 8; nt++)
        bfr[0][nt] = g_wfrag[(((size_t)(c * 12 + 0) * 4 + 0) * 16 + n2 * 8 + nt) * 32 + lane];

    // Prologue: raw0+raw1 in flight; transform chunk 0 fully.
    issue_raw(smem, tid, n, h, 0);
    issue_raw(smem, tid, n, h, 1);
    asm volatile("cp.async.wait_group 1;\n");   // raw0 complete
    __syncthreads();
#pragma unroll
    for (int p = 0; p < 8; p++) {
        __half2 d[4];
        tr_load(smem, 0, p * 256 + tid, d);
        tr_store(smem, 0, p * 256 + tid, d);
    }

    int rl  = lane & 15;
    int cl2 = (lane >> 4) * 8;

    for (int s = 0; s < 12; s++) {
        // wait raw(s+1) -> transform(s+1) may read it; barrier publishes
        // transform(s) (V[s&1]) to all warps.
        asm volatile("cp.async.wait_group 0;\n");
        __syncthreads();

        // Slot s&1 held raw(s), consumed by transform(s) last chunk -> reuse.
        if (s + 2 < 12) issue_raw(smem, tid, n, h, s + 2);

        const char* sVc = smem + V_OFF + (s & 1) * VBUF_SZ + c * VCOORD_SZ;
#pragma unroll
        for (int kt = 0; kt < 4; kt++) {
            int cur = kt & 1, nxt = cur ^ 1;
            // Prefetch next kt's B (or next chunk's kt0) into the other buffer.
            if (!(s == 11 && kt == 3)) {
                int s2  = (kt < 3) ? s : s + 1;
                int kt2 = (kt < 3) ? kt + 1 : 0;
                const uint2* gBn = g_wfrag
                    + (((size_t)(c * 12 + s2) * 4 + kt2) * 16 + n2 * 8) * 32 + lane;
#pragma unroll
                for (int nt = 0; nt < 8; nt++)
                    bfr[nxt][nt] = gBn[nt * 32];
            }

            // Transform loads for chunk s+1 (2 items), issued early: results
            // needed only after mt=1 / mt=3 MMA groups.
            __half2 d0v[4], d1v[4];
            if (s < 11) {
                tr_load(smem, s + 1, kt * 512 + tid, d0v);
                tr_load(smem, s + 1, kt * 512 + 256 + tid, d1v);
            }

#pragma unroll
            for (int mt = 0; mt < 4; mt++) {
                uint32_t a[4];
                uint32_t addr = (uint32_t)__cvta_generic_to_shared(
                    sVc + ((mt * 16 + rl) * A_PAD + kt * 16 + cl2) * 2);
                asm volatile(
                    "ldmatrix.sync.aligned.m8n8.x4.shared.b16 {%0,%1,%2,%3}, [%4];"
                    : "=r"(a[0]), "=r"(a[1]), "=r"(a[2]), "=r"(a[3])
                    : "r"(addr));
#pragma unroll
                for (int nt = 0; nt < 8; nt++)
                    asm volatile(
                        "mma.sync.aligned.m16n8k16.row.col.f16.f16.f16.f16 "
                        "{%0,%1}, {%2,%3,%4,%5}, {%6,%7}, {%0,%1};"
                        : "+r"(acc[mt][nt][0]), "+r"(acc[mt][nt][1])
                        : "r"(a[0]), "r"(a[1]), "r"(a[2]), "r"(a[3]),
                          "r"(bfr[cur][nt].x), "r"(bfr[cur][nt].y));

                // Drain transform stores inside the tensor window.
                if (s < 11 && mt == 1) tr_store(smem, s + 1, kt * 512 + tid, d0v);
                if (s < 11 && mt == 3) tr_store(smem, s + 1, kt * 512 + 256 + tid, d1v);
            }
        }
    }

    // ---- Epilogue: inverse transform y0=M0+M1+M2, y1=M1-M2-M3, * alpha[w] ----
    __syncthreads();
    __half* Vr = (__half*)(smem + V_OFF);    // [coord4][tile64][co 132-pad]
#pragma unroll
    for (int mt = 0; mt < 4; mt++) {
        int r1 = mt * 16 + (lane >> 2);      // tile index
#pragma unroll
        for (int nt = 0; nt < 8; nt++) {
            int co0 = n2 * 64 + nt * 8 + (lane & 3) * 2;
            *(uint32_t*)&Vr[((size_t)(c * 64 + r1) * 132) + co0]     = acc[mt][nt][0];
            *(uint32_t*)&Vr[((size_t)(c * 64 + r1 + 8) * 132) + co0] = acc[mt][nt][1];
        }
    }
    __syncthreads();

    float al[4];
#pragma unroll
    for (int k = 0; k < 4; k++) al[k] = g_alpha[lane + k * 32];

#pragma unroll
    for (int q = 0; q < 16; q++) {
        int co = wid * 16 + q;
        float* ob = out + (((size_t)n * C_OUT + co) * HW + h) * HW;
#pragma unroll
        for (int k = 0; k < 4; k++) {
            int w = lane + k * 32;
            int t = w >> 1, p = w & 1;
            float m0 = __half2float(Vr[(size_t)(0 * 64 + t) * 132 + co]);
            float m1 = __half2float(Vr[(size_t)(1 * 64 + t) * 132 + co]);
            float m2 = __half2float(Vr[(size_t)(2 * 64 + t) * 132 + co]);
            float m3 = __half2float(Vr[(size_t)(3 * 64 + t) * 132 + co]);
            float y = p ? (m1 - m2 - m3) : (m0 + m1 + m2);
            ob[w] = y * al[k];
        }
    }
}

// ---------------------------------------------------------------------------
extern "C" void kernel_launch(void* const* d_in, const int* in_sizes, int n_in,
                              void* d_out, int out_size) {
    (void)in_sizes; (void)n_in; (void)out_size;
    const float* x = (const float*)d_in[0];
    const float* w = (const float*)d_in[1];
    float* out = (float*)d_out;

    cudaFuncSetAttribute(conv_kernel,
                         cudaFuncAttributeMaxDynamicSharedMemorySize, SMEM_DYN);

    dim3 pg(4, 4, N_IMG * HW);
    dim3 pb(32, 8);
    pack_x_kernel<<<pg, pb>>>(x);
    pack_w_kernel<<<384, 256>>>(w);
    alpha_kernel<<<C_OUT, 256>>>(w);
    conv_kernel<<<dim3(HW, N_IMG), 256, SMEM_DYN>>>(out);
}

// round 14
// speedup vs baseline: 1.1430x; 1.1430x over previous
#include <cuda_runtime.h>
#include <cuda_fp16.h>
#include <cstdint>

#define N_IMG 16
#define C_IN  256
#define HW    128
#define C_OUT 128
#define HALO  130

// Scratch (module-load allocated; zero-initialized => halo stays zero forever)
__device__ __align__(1024) __half g_xb[(size_t)N_IMG * HALO * HALO * C_IN];
// Winograd-transformed weights, B-fragment order: [coord4][chunk12][kt4][nt16][lane32]
__device__ __align__(16) uint2 g_wfrag[4 * 12 * 4 * 16 * 32];
__device__ float g_alpha[C_OUT];

__device__ __forceinline__ float sgnf(float v) {
    return (v > 0.f) ? 1.f : ((v < 0.f) ? -1.f : 0.f);
}

// ---------------------------------------------------------------------------
// Kernel 1: sign(x) NCHW f32 -> NHWC f16 with +1 halo offset (zero padding)
// ---------------------------------------------------------------------------
__global__ void pack_x_kernel(const float* __restrict__ x) {
    __shared__ float tile[64][33];
    int nh = blockIdx.z;              // n*128 + h
    int n = nh >> 7, h = nh & 127;
    int wt = blockIdx.y;              // 0..3  (w tile of 32)
    int ct = blockIdx.x;              // 0..3  (c tile of 64)
    int tx = threadIdx.x, ty = threadIdx.y;

#pragma unroll
    for (int j = 0; j < 8; j++) {
        int cl = ty + j * 8;          // 0..63
        float v = x[(((size_t)(n * C_IN + ct * 64 + cl)) * HW + h) * HW + wt * 32 + tx];
        tile[cl][tx] = sgnf(v);
    }
    __syncthreads();
#pragma unroll
    for (int j = 0; j < 4; j++) {
        int wl = ty + j * 8;          // 0..31
        __half2 hv = __floats2half2_rn(tile[tx * 2][wl], tile[tx * 2 + 1][wl]);
        size_t dsth2 = ((((size_t)n * HALO + (h + 1)) * HALO + (wt * 32 + wl + 1)) * C_IN
                        + ct * 64) >> 1;
        reinterpret_cast<__half2*>(g_xb)[dsth2 + tx] = hv;
    }
}

// ---------------------------------------------------------------------------
// Kernel 2: sign(W) OIHW -> Winograd F(2,3) weight transform along kx,
//   packed in mma.m16n8k16 B-fragment order.
//   U0 = g0, U1 = (g0+g1+g2)/2, U2 = (g0-g1+g2)/2, U3 = g2  (g = sign(w))
// ---------------------------------------------------------------------------
__global__ void pack_w_kernel(const float* __restrict__ w) {
    int g = blockIdx.x * 256 + threadIdx.x;    // 98304 total
    int lane = g & 31;
    int nt   = (g >> 5) & 15;
    int kt   = (g >> 9) & 3;
    int idx  = g >> 11;                        // 0..47 = c*12 + chunk
    int c = idx / 12, chunk = idx % 12;
    int ky = chunk >> 2, cc = chunk & 3;

    int ci0 = cc * 64 + kt * 16 + (lane & 3) * 2;
    int co  = nt * 8 + (lane >> 2);

    uint32_t bits[4];
    int cis[4] = {ci0, ci0 + 1, ci0 + 8, ci0 + 9};
#pragma unroll
    for (int j = 0; j < 4; j++) {
        const float* wp = w + ((size_t)(co * C_IN + cis[j]) * 3 + ky) * 3;
        float g0 = sgnf(wp[0]), g1 = sgnf(wp[1]), g2 = sgnf(wp[2]);
        float u = (c == 0) ? g0
                : (c == 1) ? 0.5f * (g0 + g1 + g2)
                : (c == 2) ? 0.5f * (g0 - g1 + g2)
                :            g2;
        __half hu = __float2half(u);
        bits[j] = (uint32_t)*reinterpret_cast<uint16_t*>(&hu);
    }
    g_wfrag[g] = make_uint2(bits[0] | (bits[1] << 16), bits[2] | (bits[3] << 16));
}

// ---------------------------------------------------------------------------
// Kernel 3: alpha[co] = mean |W[co,:,:,:]|
// ---------------------------------------------------------------------------
__global__ void alpha_kernel(const float* __restrict__ w) {
    __shared__ float red[256];
    int co = blockIdx.x;
    float s = 0.f;
    for (int i = threadIdx.x; i < 2304; i += 256)
        s += fabsf(w[(size_t)co * 2304 + i]);
    red[threadIdx.x] = s;
    __syncthreads();
    for (int o = 128; o > 0; o >>= 1) {
        if (threadIdx.x < o) red[threadIdx.x] += red[threadIdx.x + o];
        __syncthreads();
    }
    if (threadIdx.x == 0) g_alpha[co] = red[0] / 2304.f;
}

// ---------------------------------------------------------------------------
// Kernel 4: Winograd-F(2,3)-along-w conv, REGISTER-SPACE input transform.
//   Raw rows stored even/odd split => d0..d3 are plain ldmatrix loads and
//   coord fragments are elementwise HADD2 in registers. No V smem buffer.
//   8 warps = (mh 0..1: 32 tiles) x (nq 0..3: 32 couts), each warp does all
//   4 coords. 3-stage raw ring, 2 CTAs/SM.
// ---------------------------------------------------------------------------
#define A_PAD 72                          // halves; 144B row stride
#define ESZ (66 * 144)                    // even/odd sub-buffer: 9504 B
#define RAWSZ (2 * ESZ)                   // 19008 per stage
#define RAW_STAGES 3
#define VR_SZ (4 * 64 * 132 * 2)          // epilogue buffer 67584 (reuses ring)
#define SMEM_DYN VR_SZ                    // 67584 >= 3*RAWSZ=57024; x2 CTA fits

__device__ __forceinline__ void issue_raw(char* smem, int tid, int n, int h, int s) {
    int ky = s >> 2, cc = s & 3;
    char* sR = smem + (s % 3) * RAWSZ;
    const __half* gx = &g_xb[(((size_t)n * HALO + h + ky) * HALO) * C_IN + cc * 64];
#pragma unroll
    for (int v = 0; v < 5; v++) {
        int u = tid + v * 256;            // 1040 units of 16B (130 pixel rows x 8)
        if (u < 130 * 8) {
            int p = u >> 3, seg = u & 7;
            // even/odd split: pixel p -> buffer (p&1), row p>>1
            uint32_t sa = (uint32_t)__cvta_generic_to_shared(
                sR + (p & 1) * ESZ + (p >> 1) * 144 + seg * 16);
            const void* ga = gx + (size_t)p * C_IN + seg * 8;
            asm volatile("cp.async.cg.shared.global [%0], [%1], 16;\n" :: "r"(sa), "l"(ga));
        }
    }
    asm volatile("cp.async.commit_group;\n");
}

#define LDSM(dst, ptr)                                                         \
    asm volatile(                                                              \
        "ldmatrix.sync.aligned.m8n8.x4.shared.b16 {%0,%1,%2,%3}, [%4];"        \
        : "=r"((dst)[0]), "=r"((dst)[1]), "=r"((dst)[2]), "=r"((dst)[3])       \
        : "r"((uint32_t)__cvta_generic_to_shared(ptr)))

__global__ void __launch_bounds__(256, 2) conv_kernel(float* __restrict__ out) {
    extern __shared__ char smem[];
    int tid = threadIdx.x;
    int lane = tid & 31, wid = tid >> 5;
    int mh = wid >> 2;        // 0..1 : 32-tile M half
    int nq = wid & 3;         // 0..3 : 32-cout N quarter
    int h = blockIdx.x, n = blockIdx.y;

    uint32_t acc[4][2][4][2];   // [coord][mt][nt][half] f16x2
#pragma unroll
    for (int a = 0; a < 4; a++)
#pragma unroll
        for (int b = 0; b < 2; b++)
#pragma unroll
            for (int d = 0; d < 4; d++) { acc[a][b][d][0] = 0u; acc[a][b][d][1] = 0u; }

    issue_raw(smem, tid, n, h, 0);
    issue_raw(smem, tid, n, h, 1);

    int rl  = lane & 15;            // ldmatrix row-within-16
    int cl2 = (lane >> 4) * 8;      // ldmatrix col half-select (halves)

    for (int s = 0; s < 12; s++) {
        if (s < 11) asm volatile("cp.async.wait_group 1;\n");
        else        asm volatile("cp.async.wait_group 0;\n");
        __syncthreads();
        // slot (s+2)%3 held raw(s-1), fully consumed during iter s-1.
        if (s + 2 < 12) issue_raw(smem, tid, n, h, s + 2);

        const char* rE = smem + (s % 3) * RAWSZ;
        const char* rO = rE + ESZ;

#pragma unroll
        for (int kt = 0; kt < 4; kt++) {
            // ---- A: ldsm raw even/odd pairs, transform in registers ----
            uint32_t vf[2][4][4];   // [mt][coord][fragreg]
#pragma unroll
            for (int mt = 0; mt < 2; mt++) {
                int trow = mh * 32 + mt * 16 + rl;
                int boff = (trow * A_PAD + kt * 16 + cl2) * 2;
                uint32_t d0[4], d1[4], d2[4], d3[4];
                LDSM(d0, rE + boff);
                LDSM(d2, rE + boff + 144);
                LDSM(d1, rO + boff);
                LDSM(d3, rO + boff + 144);
#pragma unroll
                for (int r = 0; r < 4; r++) {
                    __half2 h0 = *(__half2*)&d0[r], h1 = *(__half2*)&d1[r];
                    __half2 h2 = *(__half2*)&d2[r], h3 = *(__half2*)&d3[r];
                    __half2 v0 = __hsub2(h0, h2);
                    __half2 v1 = __hadd2(h1, h2);
                    __half2 v2 = __hsub2(h2, h1);
                    __half2 v3 = __hsub2(h1, h3);
                    vf[mt][0][r] = *(uint32_t*)&v0;
                    vf[mt][1][r] = *(uint32_t*)&v1;
                    vf[mt][2][r] = *(uint32_t*)&v2;
                    vf[mt][3][r] = *(uint32_t*)&v3;
                }
            }

            // ---- B double-buffered per coord; MMAs ----
            uint2 bb[2][4];
#pragma unroll
            for (int nt = 0; nt < 4; nt++)
                bb[0][nt] = g_wfrag[(((size_t)(0 * 12 + s) * 4 + kt) * 16
                                     + nq * 4 + nt) * 32 + lane];
#pragma unroll
            for (int c = 0; c < 4; c++) {
                if (c < 3) {
#pragma unroll
                    for (int nt = 0; nt < 4; nt++)
                        bb[(c + 1) & 1][nt] =
                            g_wfrag[(((size_t)((c + 1) * 12 + s) * 4 + kt) * 16
                                     + nq * 4 + nt) * 32 + lane];
                }
#pragma unroll
                for (int mt = 0; mt < 2; mt++)
#pragma unroll
                    for (int nt = 0; nt < 4; nt++)
                        asm volatile(
                            "mma.sync.aligned.m16n8k16.row.col.f16.f16.f16.f16 "
                            "{%0,%1}, {%2,%3,%4,%5}, {%6,%7}, {%0,%1};"
                            : "+r"(acc[c][mt][nt][0]), "+r"(acc[c][mt][nt][1])
                            : "r"(vf[mt][c][0]), "r"(vf[mt][c][1]),
                              "r"(vf[mt][c][2]), "r"(vf[mt][c][3]),
                              "r"(bb[c & 1][nt].x), "r"(bb[c & 1][nt].y));
            }
        }
    }

    // ---- Epilogue: inverse transform y0=M0+M1+M2, y1=M1-M2-M3, * alpha[w] ----
    __syncthreads();
    __half* Vr = (__half*)smem;     // [coord4][tile64][co 132-pad], reuses ring
#pragma unroll
    for (int c = 0; c < 4; c++)
#pragma unroll
        for (int mt = 0; mt < 2; mt++) {
            int r1 = mh * 32 + mt * 16 + (lane >> 2);
#pragma unroll
            for (int nt = 0; nt < 4; nt++) {
                int co0 = nq * 32 + nt * 8 + (lane & 3) * 2;
                *(uint32_t*)&Vr[((size_t)(c * 64 + r1) * 132) + co0]     = acc[c][mt][nt][0];
                *(uint32_t*)&Vr[((size_t)(c * 64 + r1 + 8) * 132) + co0] = acc[c][mt][nt][1];
            }
        }
    __syncthreads();

    float al[4];
#pragma unroll
    for (int k = 0; k < 4; k++) al[k] = g_alpha[lane + k * 32];

#pragma unroll
    for (int q = 0; q < 16; q++) {
        int co = wid * 16 + q;
        float* ob = out + (((size_t)n * C_OUT + co) * HW + h) * HW;
#pragma unroll
        for (int k = 0; k < 4; k++) {
            int w = lane + k * 32;
            int t = w >> 1, p = w & 1;
            float m0 = __half2float(Vr[(size_t)(0 * 64 + t) * 132 + co]);
            float m1 = __half2float(Vr[(size_t)(1 * 64 + t) * 132 + co]);
            float m2 = __half2float(Vr[(size_t)(2 * 64 + t) * 132 + co]);
            float m3 = __half2float(Vr[(size_t)(3 * 64 + t) * 132 + co]);
            float y = p ? (m1 - m2 - m3) : (m0 + m1 + m2);
            ob[w] = y * al[k];
        }
    }
}

// ---------------------------------------------------------------------------
extern "C" void kernel_launch(void* const* d_in, const int* in_sizes, int n_in,
                              void* d_out, int out_size) {
    (void)in_sizes; (void)n_in; (void)out_size;
    const float* x = (const float*)d_in[0];
    const float* w = (const float*)d_in[1];
    float* out = (float*)d_out;

    cudaFuncSetAttribute(conv_kernel,
                         cudaFuncAttributeMaxDynamicSharedMemorySize, SMEM_DYN);

    dim3 pg(4, 4, N_IMG * HW);
    dim3 pb(32, 8);
    pack_x_kernel<<<pg, pb>>>(x);
    pack_w_kernel<<<384, 256>>>(w);
    alpha_kernel<<<C_OUT, 256>>>(w);
    conv_kernel<<<dim3(HW, N_IMG), 256, SMEM_DYN>>>(out);
}